// round 10
// baseline (speedup 1.0000x reference)
#include <cuda_runtime.h>
#include <cstdint>

#define BB    2
#define CC    64
#define NPOS  131072
#define HEADS 4
#define DHEAD 32
#define HID   128
#define TPB   128
#define POSB  128

typedef unsigned long long u64;

// ---------------- device scratch ----------------
__device__ float g_ctx[BB * HEADS * DHEAD * DHEAD];
__device__ float g_Z[BB * HEADS * DHEAD];
__device__ float g_M[BB * HID * CC];            // M[b][h*32+d][o], o contiguous

// ---------------- f32x2 helpers ----------------
__device__ __forceinline__ u64 pack2(float lo, float hi) {
    u64 r; asm("mov.b64 %0, {%1,%2};" : "=l"(r) : "f"(lo), "f"(hi)); return r;
}
__device__ __forceinline__ u64 ffma2(u64 a, u64 b, u64 c) {
    u64 d; asm("fma.rn.f32x2 %0, %1, %2, %3;" : "=l"(d) : "l"(a), "l"(b), "l"(c)); return d;
}
__device__ __forceinline__ u64 fadd2(u64 a, u64 b) {
    u64 d; asm("add.rn.f32x2 %0, %1, %2;" : "=l"(d) : "l"(a), "l"(b)); return d;
}
__device__ __forceinline__ float hsum2(u64 a) {
    float lo, hi; asm("mov.b64 {%0,%1}, %2;" : "=f"(lo), "=f"(hi) : "l"(a)); return lo + hi;
}
__device__ __forceinline__ void unpack2(u64 a, float& lo, float& hi) {
    asm("mov.b64 {%0,%1}, %2;" : "=f"(lo), "=f"(hi) : "l"(a));
}

// ---------------- kernel 0: zero accumulators ----------------
__global__ void la_zero_kernel() {
    int i = blockIdx.x * blockDim.x + threadIdx.x;
    if (i < BB * HEADS * DHEAD * DHEAD) g_ctx[i] = 0.f;
    if (i < BB * HEADS * DHEAD)         g_Z[i]   = 0.f;
}

// =================== shared building blocks (TPB=128) ===================
// W chunk 32 rows x 64 k, smem duplicated: wd[k*34 + row] = (w,w).
__device__ __forceinline__ void wchunk_ldg(float (&wr)[16], const float* __restrict__ wsrc, int t) {
#pragma unroll
    for (int i = 0; i < 16; i++) wr[i] = __ldg(wsrc + t + i * 128);
}
__device__ __forceinline__ void wchunk_sts(u64* wd, const float (&wr)[16], int t) {
#pragma unroll
    for (int i = 0; i < 16; i++) {
        int p = t + i * 128;                  // p = row*64 + k
        wd[(p & 63) * 34 + (p >> 6)] = pack2(wr[i], wr[i]);
    }
}

// GEMM tile: 32 rows x 128 pos; thread = 8 rows (rg=t>>5, warp-uniform) x 4 pos (pg=t&31).
// Per k: 4 broadcast LDS.128 (W dup) + 1 contiguous LDS.128 (x pairs) + 16 FFMA2.
__device__ __forceinline__ void gemm8x4(const u64* __restrict__ wd, const float* __restrict__ xs,
                                        int rg, int pg, u64 (&acc)[8][2]) {
#pragma unroll
    for (int r = 0; r < 8; r++) { acc[r][0] = 0; acc[r][1] = 0; }
#pragma unroll 4
    for (int k = 0; k < 64; k++) {
        const u64* wk = wd + k * 34 + rg * 8;
        ulonglong2 w01 = *(const ulonglong2*)(wk);
        ulonglong2 w23 = *(const ulonglong2*)(wk + 2);
        ulonglong2 w45 = *(const ulonglong2*)(wk + 4);
        ulonglong2 w67 = *(const ulonglong2*)(wk + 6);
        ulonglong2 xv  = *(const ulonglong2*)(xs + k * 132 + pg * 4);
        acc[0][0] = ffma2(w01.x, xv.x, acc[0][0]); acc[0][1] = ffma2(w01.x, xv.y, acc[0][1]);
        acc[1][0] = ffma2(w01.y, xv.x, acc[1][0]); acc[1][1] = ffma2(w01.y, xv.y, acc[1][1]);
        acc[2][0] = ffma2(w23.x, xv.x, acc[2][0]); acc[2][1] = ffma2(w23.x, xv.y, acc[2][1]);
        acc[3][0] = ffma2(w23.y, xv.x, acc[3][0]); acc[3][1] = ffma2(w23.y, xv.y, acc[3][1]);
        acc[4][0] = ffma2(w45.x, xv.x, acc[4][0]); acc[4][1] = ffma2(w45.x, xv.y, acc[4][1]);
        acc[5][0] = ffma2(w45.y, xv.x, acc[5][0]); acc[5][1] = ffma2(w45.y, xv.y, acc[5][1]);
        acc[6][0] = ffma2(w67.x, xv.x, acc[6][0]); acc[6][1] = ffma2(w67.x, xv.y, acc[6][1]);
        acc[7][0] = ffma2(w67.y, xv.x, acc[7][0]); acc[7][1] = ffma2(w67.y, xv.y, acc[7][1]);
    }
}

__device__ __forceinline__ void tile_store(float* __restrict__ dst, const u64 (&acc)[8][2],
                                           int rg, int pg, bool do_exp) {
#pragma unroll
    for (int r = 0; r < 8; r++) {
        int row = rg * 8 + r;
#pragma unroll
        for (int pp = 0; pp < 2; pp++) {
            float lo, hi; unpack2(acc[r][pp], lo, hi);
            if (do_exp) { lo = __expf(lo); hi = __expf(hi); }
            *(u64*)(dst + row * 132 + pg * 4 + pp * 2) = pack2(lo, hi);
        }
    }
}

// phase0: per-position channel-LN, 1 thread per position. Raw stage into xs, then
// normalize in place (keeps register pressure low).
__device__ __forceinline__ void phase0_ln(const float* __restrict__ x, int bb, int pos0,
                                          int t, float* xs,
                                          const float* g1s, const float* b1s) {
    const float* xb = x + (size_t)bb * CC * NPOS + pos0 + t;
    u64 sa = 0, s2a = 0;
#pragma unroll
    for (int i = 0; i < 32; i++) {
        float a  = __ldg(xb + (size_t)(2 * i)     * NPOS);
        float bv = __ldg(xb + (size_t)(2 * i + 1) * NPOS);
        u64 p = pack2(a, bv);
        sa = fadd2(sa, p); s2a = ffma2(p, p, s2a);
        xs[(2 * i)     * 132 + t] = a;
        xs[(2 * i + 1) * 132 + t] = bv;
    }
    float s = hsum2(sa), s2 = hsum2(s2a);
    float mean = s * (1.f / 64.f);
    float rstd = rsqrtf(s2 * (1.f / 64.f) - mean * mean + 1e-5f);
    __syncthreads();                      // g1s/b1s ready (own xs column needs no sync)
#pragma unroll
    for (int ch = 0; ch < 64; ch++) {
        float v = xs[ch * 132 + t];
        xs[ch * 132 + t] = (v - mean) * rstd * g1s[ch] + b1s[ch];
    }
}

// ================= pass1: LN1 + K,V GEMMs + ctx/Z partials =================
// smem: wdA[2176]u64 wdB[2176]u64 xs[64*132] ek[32*132] vv[32*132] g1s/b1s
#define SM1_FLOATS (4352 + 4352 + 64 * 132 + 32 * 132 + 32 * 132 + 128)   // 25728 fl

__global__ __launch_bounds__(TPB, 2)
void la_pass1_kernel(const float* __restrict__ x, const float* __restrict__ g1,
                     const float* __restrict__ b1, const float* __restrict__ wqkv) {
    extern __shared__ float sm1[];
    u64*   wdA = (u64*)sm1;
    u64*   wdB = wdA + 2176;
    float* xs  = sm1 + 8704;
    float* ek  = xs + 64 * 132;
    float* vv  = ek + 32 * 132;
    float* g1s = vv + 32 * 132;
    float* b1s = g1s + 64;

    const int t    = threadIdx.x;
    const int bb   = blockIdx.y;
    const int pos0 = blockIdx.x * POSB;

    float wr[16];
    wchunk_ldg(wr, wqkv + (size_t)HID * 64, t);            // K head 0
    if (t < 64) { g1s[t] = g1[t]; b1s[t] = b1[t]; }
    phase0_ln(x, bb, pos0, t, xs, g1s, b1s);
    wchunk_sts(wdA, wr, t);
    __syncthreads();

    const int rg = t >> 5, pg = t & 31;
    const int d_own = t >> 2, e0 = t & 3;

    u64 acc[8][2];
    for (int h = 0; h < HEADS; h++) {
        // interval 1: ldg V_h; GEMM K(wdA) -> ek (exp); sts V -> wdB
        wchunk_ldg(wr, wqkv + (size_t)(2 * HID + h * 32) * 64, t);
        gemm8x4(wdA, xs, rg, pg, acc);
        tile_store(ek, acc, rg, pg, true);
        wchunk_sts(wdB, wr, t);
        __syncthreads();

        // interval 2: GEMM V(wdB) -> vv; ldg+sts K_{h+1} -> wdA
        if (h < 3) wchunk_ldg(wr, wqkv + (size_t)(HID + (h + 1) * 32) * 64, t);
        gemm8x4(wdB, xs, rg, pg, acc);
        tile_store(vv, acc, rg, pg, false);
        if (h < 3) wchunk_sts(wdA, wr, t);
        __syncthreads();

        // interval 3: stage B: ctx[d][e] += sum_pos ek[d]*vv[e];  Z[d] += sum ek[d]
        {
            u64 a[8]; 
#pragma unroll
            for (int j = 0; j < 8; j++) a[j] = 0;
            u64 za = 0;
            const float* ekr = ek + d_own * 132;
#pragma unroll 2
            for (int tt = 0; tt < POSB; tt += 4) {
                ulonglong2 ap = *(const ulonglong2*)(ekr + tt);
#pragma unroll
                for (int j = 0; j < 8; j++) {
                    ulonglong2 bv = *(const ulonglong2*)(vv + (e0 + 4 * j) * 132 + tt);
                    a[j] = ffma2(ap.x, bv.x, a[j]);
                    a[j] = ffma2(ap.y, bv.y, a[j]);
                }
                if (e0 == 0) za = fadd2(za, fadd2(ap.x, ap.y));
            }
            float* cb = g_ctx + (size_t)((bb * HEADS + h) * DHEAD + d_own) * DHEAD;
#pragma unroll
            for (int j = 0; j < 8; j++) atomicAdd(cb + e0 + 4 * j, hsum2(a[j]));
            if (e0 == 0) atomicAdd(g_Z + (bb * HEADS + h) * DHEAD + d_own, hsum2(za));
        }
        __syncthreads();
    }
}

// ---------------- kernel 2: fold  M[b][h*32+d][o] ----------------
__global__ void la_fold_kernel(const float* __restrict__ wout) {
    int bb = blockIdx.x;
    for (int idx = threadIdx.x; idx < HID * CC; idx += blockDim.x) {
        int i = idx >> 6, o = idx & 63;
        int h = i >> 5,   d = i & 31;
        const float* cp = g_ctx + (size_t)((bb * HEADS + h) * DHEAD + d) * DHEAD;
        const float* wp = wout + (size_t)o * HID + h * DHEAD;
        float acc = 0.f;
#pragma unroll
        for (int e = 0; e < 32; e++) acc += wp[e] * cp[e];
        g_M[(size_t)bb * HID * CC + i * 64 + o] = acc / g_Z[(bb * HEADS + h) * DHEAD + d];
    }
}

// ===== pass2: LN1 + Q GEMM + softmax + y += M_h q_h + LN2 (q stays on-chip) =====
// smem: wdA[2176]u64 md[2112]u64 xs[64*132] ekq[32*132] params(320)
#define SM2_FLOATS (4352 + 4224 + 64 * 132 + 32 * 132 + 320)   // 21568 fl

__global__ __launch_bounds__(TPB, 2)
void la_pass2_kernel(const float* __restrict__ x, const float* __restrict__ g1,
                     const float* __restrict__ b1, const float* __restrict__ wqkv,
                     const float* __restrict__ bout, const float* __restrict__ g2,
                     const float* __restrict__ b2, float* __restrict__ out) {
    extern __shared__ float sm2[];
    u64*   wdA = (u64*)sm2;                  // Q chunk, dup
    u64*   md  = wdA + 2176;                 // M dup: md[d*66 + o] = (M,M)
    float* xs  = sm2 + 8576;
    float* ekq = xs + 64 * 132;
    float* bo  = ekq + 32 * 132;
    float* g2s = bo + 64;
    float* b2s = g2s + 64;
    float* g1s = b2s + 64;
    float* b1s = g1s + 64;

    const int t    = threadIdx.x;
    const int bb   = blockIdx.y;
    const int pos0 = blockIdx.x * POSB;

    float wr[16];
    wchunk_ldg(wr, wqkv, t);                               // Q head 0
    if (t < 64) {
        bo[t] = bout[t]; g2s[t] = g2[t]; b2s[t] = b2[t];
        g1s[t] = g1[t];  b1s[t] = b1[t];
    }
    phase0_ln(x, bb, pos0, t, xs, g1s, b1s);
    wchunk_sts(wdA, wr, t);
    __syncthreads();

    const int rg = t >> 5, pg = t & 31;
    const int og = t & 7,  pg2 = t >> 3;       // M-apply: 8 o's (og*8+..) x 8 pos (pg2*8+..)

    // acc_y[o'][pp]: o = og*8+o', pos pair pp over pg2*8+{2pp,2pp+1}
    u64 acc_y[8][4];
#pragma unroll
    for (int o = 0; o < 8; o++)
#pragma unroll
        for (int pp = 0; pp < 4; pp++) acc_y[o][pp] = 0;

    u64 acc[8][2];
    float mld[16];
    for (int h = 0; h < HEADS; h++) {
        // interval 1: ldg M_h; Q GEMM -> ekq raw
        {
            const float* mh = g_M + (size_t)bb * HID * CC + (size_t)h * 32 * 64;
#pragma unroll
            for (int i = 0; i < 16; i++) mld[i] = __ldg(mh + t + i * 128);
        }
        gemm8x4(wdA, xs, rg, pg, acc);
        tile_store(ekq, acc, rg, pg, false);
        __syncthreads();

        // interval 2: softmax own column; sts M dup; ldg+sts Q_{h+1}
        {
            float qv[32];
            float mx = -1e30f;
#pragma unroll
            for (int d = 0; d < 32; d++) { qv[d] = ekq[d * 132 + t]; mx = fmaxf(mx, qv[d]); }
            float ss = 0.f;
#pragma unroll
            for (int d = 0; d < 32; d++) { qv[d] = __expf(qv[d] - mx); ss += qv[d]; }
            float qsc = 0.17677669529663687f / ss;
#pragma unroll
            for (int d = 0; d < 32; d++) ekq[d * 132 + t] = qv[d] * qsc;
        }
#pragma unroll
        for (int i = 0; i < 16; i++) {
            int p = t + i * 128;               // p = d*64 + o
            md[(p >> 6) * 66 + (p & 63)] = pack2(mld[i], mld[i]);
        }
        if (h < 3) {
            wchunk_ldg(wr, wqkv + (size_t)(h + 1) * 32 * 64, t);
            wchunk_sts(wdA, wr, t);
        }
        __syncthreads();

        // interval 3: y += M_h @ q_h
#pragma unroll 2
        for (int d = 0; d < 32; d++) {
            const u64* mk = md + d * 66 + og * 8;
            ulonglong2 m01 = *(const ulonglong2*)(mk);
            ulonglong2 m23 = *(const ulonglong2*)(mk + 2);
            ulonglong2 m45 = *(const ulonglong2*)(mk + 4);
            ulonglong2 m67 = *(const ulonglong2*)(mk + 6);
            ulonglong2 qa = *(const ulonglong2*)(ekq + d * 132 + pg2 * 8);
            ulonglong2 qb = *(const ulonglong2*)(ekq + d * 132 + pg2 * 8 + 4);
            acc_y[0][0] = ffma2(m01.x, qa.x, acc_y[0][0]); acc_y[0][1] = ffma2(m01.x, qa.y, acc_y[0][1]);
            acc_y[0][2] = ffma2(m01.x, qb.x, acc_y[0][2]); acc_y[0][3] = ffma2(m01.x, qb.y, acc_y[0][3]);
            acc_y[1][0] = ffma2(m01.y, qa.x, acc_y[1][0]); acc_y[1][1] = ffma2(m01.y, qa.y, acc_y[1][1]);
            acc_y[1][2] = ffma2(m01.y, qb.x, acc_y[1][2]); acc_y[1][3] = ffma2(m01.y, qb.y, acc_y[1][3]);
            acc_y[2][0] = ffma2(m23.x, qa.x, acc_y[2][0]); acc_y[2][1] = ffma2(m23.x, qa.y, acc_y[2][1]);
            acc_y[2][2] = ffma2(m23.x, qb.x, acc_y[2][2]); acc_y[2][3] = ffma2(m23.x, qb.y, acc_y[2][3]);
            acc_y[3][0] = ffma2(m23.y, qa.x, acc_y[3][0]); acc_y[3][1] = ffma2(m23.y, qa.y, acc_y[3][1]);
            acc_y[3][2] = ffma2(m23.y, qb.x, acc_y[3][2]); acc_y[3][3] = ffma2(m23.y, qb.y, acc_y[3][3]);
            acc_y[4][0] = ffma2(m45.x, qa.x, acc_y[4][0]); acc_y[4][1] = ffma2(m45.x, qa.y, acc_y[4][1]);
            acc_y[4][2] = ffma2(m45.x, qb.x, acc_y[4][2]); acc_y[4][3] = ffma2(m45.x, qb.y, acc_y[4][3]);
            acc_y[5][0] = ffma2(m45.y, qa.x, acc_y[5][0]); acc_y[5][1] = ffma2(m45.y, qa.y, acc_y[5][1]);
            acc_y[5][2] = ffma2(m45.y, qb.x, acc_y[5][2]); acc_y[5][3] = ffma2(m45.y, qb.y, acc_y[5][3]);
            acc_y[6][0] = ffma2(m67.x, qa.x, acc_y[6][0]); acc_y[6][1] = ffma2(m67.x, qa.y, acc_y[6][1]);
            acc_y[6][2] = ffma2(m67.x, qb.x, acc_y[6][2]); acc_y[6][3] = ffma2(m67.x, qb.y, acc_y[6][3]);
            acc_y[7][0] = ffma2(m67.y, qa.x, acc_y[7][0]); acc_y[7][1] = ffma2(m67.y, qa.y, acc_y[7][1]);
            acc_y[7][2] = ffma2(m67.y, qb.x, acc_y[7][2]); acc_y[7][3] = ffma2(m67.y, qb.y, acc_y[7][3]);
        }
        __syncthreads();
    }

    // epilogue: bias + LN2 (channel sums via shfl over the 8 og lanes) + store
#pragma unroll
    for (int o = 0; o < 8; o++) {
        float b = bo[og * 8 + o];
        u64 bp = pack2(b, b);
#pragma unroll
        for (int pp = 0; pp < 4; pp++) acc_y[o][pp] = fadd2(acc_y[o][pp], bp);
    }
    u64 su[4] = {0, 0, 0, 0}, s2u[4] = {0, 0, 0, 0};
#pragma unroll
    for (int o = 0; o < 8; o++)
#pragma unroll
        for (int pp = 0; pp < 4; pp++) {
            su[pp]  = fadd2(su[pp], acc_y[o][pp]);
            s2u[pp] = ffma2(acc_y[o][pp], acc_y[o][pp], s2u[pp]);
        }
#pragma unroll
    for (int m = 1; m < 8; m <<= 1)
#pragma unroll
        for (int pp = 0; pp < 4; pp++) {
            su[pp]  = fadd2(su[pp],  __shfl_xor_sync(0xffffffffu, su[pp],  m));
            s2u[pp] = fadd2(s2u[pp], __shfl_xor_sync(0xffffffffu, s2u[pp], m));
        }
    float mean_[8], rstd_[8];
#pragma unroll
    for (int pp = 0; pp < 4; pp++) {
        float sa, sb, qa, qb; unpack2(su[pp], sa, sb); unpack2(s2u[pp], qa, qb);
        float ma = sa * (1.f / 64.f), mb2 = sb * (1.f / 64.f);
        mean_[2 * pp] = ma; mean_[2 * pp + 1] = mb2;
        rstd_[2 * pp]     = rsqrtf(qa * (1.f / 64.f) - ma * ma + 1e-5f);
        rstd_[2 * pp + 1] = rsqrtf(qb * (1.f / 64.f) - mb2 * mb2 + 1e-5f);
    }
    float* ob = out + (size_t)bb * CC * NPOS + pos0 + pg2 * 8;
#pragma unroll
    for (int o = 0; o < 8; o++) {
        int oc = og * 8 + o;
        float ga = g2s[oc], bv = b2s[oc];
        float4 v0, v1;
        float lo, hi;
        unpack2(acc_y[o][0], lo, hi);
        v0.x = (lo - mean_[0]) * rstd_[0] * ga + bv;
        v0.y = (hi - mean_[1]) * rstd_[1] * ga + bv;
        unpack2(acc_y[o][1], lo, hi);
        v0.z = (lo - mean_[2]) * rstd_[2] * ga + bv;
        v0.w = (hi - mean_[3]) * rstd_[3] * ga + bv;
        unpack2(acc_y[o][2], lo, hi);
        v1.x = (lo - mean_[4]) * rstd_[4] * ga + bv;
        v1.y = (hi - mean_[5]) * rstd_[5] * ga + bv;
        unpack2(acc_y[o][3], lo, hi);
        v1.z = (lo - mean_[6]) * rstd_[6] * ga + bv;
        v1.w = (hi - mean_[7]) * rstd_[7] * ga + bv;
        *(float4*)(ob + (size_t)oc * NPOS)     = v0;
        *(float4*)(ob + (size_t)oc * NPOS + 4) = v1;
    }
}

// ---------------- launch ----------------
extern "C" void kernel_launch(void* const* d_in, const int* in_sizes, int n_in,
                              void* d_out, int out_size) {
    (void)in_sizes; (void)n_in; (void)out_size;
    const float* x    = (const float*)d_in[0];
    const float* g1   = (const float*)d_in[1];
    const float* b1   = (const float*)d_in[2];
    const float* wqkv = (const float*)d_in[3];
    const float* wout = (const float*)d_in[4];
    const float* bout = (const float*)d_in[5];
    const float* g2   = (const float*)d_in[6];
    const float* b2   = (const float*)d_in[7];
    float* y = (float*)d_out;

    cudaFuncSetAttribute(la_pass1_kernel, cudaFuncAttributeMaxDynamicSharedMemorySize,
                         SM1_FLOATS * (int)sizeof(float));
    cudaFuncSetAttribute(la_pass2_kernel, cudaFuncAttributeMaxDynamicSharedMemorySize,
                         SM2_FLOATS * (int)sizeof(float));

    la_zero_kernel<<<33, 256>>>();
    la_pass1_kernel<<<dim3(NPOS / POSB, BB), TPB, SM1_FLOATS * sizeof(float)>>>(x, g1, b1, wqkv);
    la_fold_kernel<<<BB, 256>>>(wout);
    la_pass2_kernel<<<dim3(NPOS / POSB, BB), TPB, SM2_FLOATS * sizeof(float)>>>(
        x, g1, b1, wqkv, bout, g2, b2, y);
}